// round 2
// baseline (speedup 1.0000x reference)
#include <cuda_runtime.h>
#include <cuda_bf16.h>
#include <math.h>

// ---------------------------------------------------------------------------
// Problem constants (Qwen2Attention_11725260718470)
// ---------------------------------------------------------------------------
#define T_TOK   4096      // B*S tokens
#define HDIM    3584      // hidden size
#define NH      28        // query heads
#define NKV     4         // kv heads
#define DHEAD   128
#define GROUP   7         // NH / NKV
#define BATCH   4
#define SEQ     1024
#define QKV_OUT 4608      // (NH + 2*NKV) * DHEAD
#define NSLOTS  8192      // NB*BS = 512*16
#define SCALE_F 0.08838834764831845f  // 1/sqrt(128)
#define NEG_BIG (-1e30f)

// ---------------------------------------------------------------------------
// Device scratch (static allocation is allowed; runtime alloc is not)
// ---------------------------------------------------------------------------
__device__ float g_qkv[(size_t)T_TOK * QKV_OUT];        // 75.5 MB
__device__ float g_ctx[(size_t)T_TOK * NH * DHEAD];     // 58.7 MB

// ---------------------------------------------------------------------------
// Classic 128x128x8 fp32 SGEMM:  C[m,n] = sum_k A[m,K]*B[n,K] (+ bias[n])
// A: [M,K] row-major, B: [N,K] row-major (i.e. C = A @ B^T).
// ---------------------------------------------------------------------------
__global__ __launch_bounds__(256, 2)
void sgemm_tn(const float* __restrict__ A, const float* __restrict__ B,
              const float* __restrict__ bias, float* __restrict__ C,
              int M, int N, int K) {
    constexpr int BM = 128, BN = 128, BK = 8;
    __shared__ float As[BK][BM];
    __shared__ float Bs[BK][BN];

    const int tid = threadIdx.x;
    const int bm = blockIdx.y * BM;
    const int bn = blockIdx.x * BN;

    const int lr = tid >> 1;          // 0..127  (row within tile)
    const int lc = (tid & 1) * 4;     // 0 or 4  (k offset)
    const float* Ap = A + (size_t)(bm + lr) * K + lc;
    const float* Bp = B + (size_t)(bn + lr) * K + lc;

    const int tx = tid & 15;          // 0..15 -> 8 output cols each
    const int ty = tid >> 4;          // 0..15 -> 8 output rows each

    float acc[8][8];
    #pragma unroll
    for (int i = 0; i < 8; i++)
        #pragma unroll
        for (int j = 0; j < 8; j++) acc[i][j] = 0.f;

    for (int k0 = 0; k0 < K; k0 += BK) {
        float4 av = *(const float4*)(Ap + k0);
        float4 bv = *(const float4*)(Bp + k0);
        As[lc + 0][lr] = av.x; As[lc + 1][lr] = av.y;
        As[lc + 2][lr] = av.z; As[lc + 3][lr] = av.w;
        Bs[lc + 0][lr] = bv.x; Bs[lc + 1][lr] = bv.y;
        Bs[lc + 2][lr] = bv.z; Bs[lc + 3][lr] = bv.w;
        __syncthreads();

        #pragma unroll
        for (int kk = 0; kk < BK; kk++) {
            float ar[8], br[8];
            #pragma unroll
            for (int i = 0; i < 8; i++) ar[i] = As[kk][ty * 8 + i];
            #pragma unroll
            for (int j = 0; j < 8; j++) br[j] = Bs[kk][tx * 8 + j];
            #pragma unroll
            for (int i = 0; i < 8; i++)
                #pragma unroll
                for (int j = 0; j < 8; j++)
                    acc[i][j] += ar[i] * br[j];
        }
        __syncthreads();
    }

    #pragma unroll
    for (int i = 0; i < 8; i++) {
        const int m = bm + ty * 8 + i;
        #pragma unroll
        for (int j = 0; j < 8; j += 4) {
            const int n = bn + tx * 8 + j;
            float4 v;
            float b0 = bias ? bias[n + 0] : 0.f;
            float b1 = bias ? bias[n + 1] : 0.f;
            float b2 = bias ? bias[n + 2] : 0.f;
            float b3 = bias ? bias[n + 3] : 0.f;
            v.x = acc[i][j + 0] + b0;
            v.y = acc[i][j + 1] + b1;
            v.z = acc[i][j + 2] + b2;
            v.w = acc[i][j + 3] + b3;
            *(float4*)(C + (size_t)m * N + n) = v;
        }
    }
}

// ---------------------------------------------------------------------------
// RoPE (q and k) + scatter k/v into the output cache.
// FIX vs prior round: sincos argument order (sin first!), and fp64 trig so
// the cache matches JAX's accurate f32 sin/cos even under --use_fast_math.
// ---------------------------------------------------------------------------
__global__ void rope_scatter_kernel(const int* __restrict__ positions,
                                    const int* __restrict__ slot_mapping,
                                    float* __restrict__ cache_out) {
    const int t = blockIdx.x;
    const int tid = threadIdx.x;
    const int pos = positions[t];
    float* row = g_qkv + (size_t)t * QKV_OUT;
    const int slot = slot_mapping[t];
    float* kout = cache_out + (size_t)slot * NKV * DHEAD;
    float* vout = cache_out + (size_t)NSLOTS * NKV * DHEAD + (size_t)slot * NKV * DHEAD;

    if (tid < 64) {
        // inv_freq[i] = theta^(-i/64) computed accurately in f32 (matches jax),
        // then angle/trig in fp64 to avoid fast-math range-reduction error.
        const float invf = expf(-(float)tid * (logf(10000.f) / 64.f));
        const double ang = (double)pos * (double)invf;
        double dc, ds;
        sincos(ang, &ds, &dc);          // sin first, cos second (correct order)
        const float c = (float)dc;
        const float s = (float)ds;

        #pragma unroll 4
        for (int h = 0; h < NH; h++) {
            float* x = row + h * DHEAD;
            float x1 = x[tid], x2 = x[tid + 64];
            x[tid]      = x1 * c - x2 * s;
            x[tid + 64] = x2 * c + x1 * s;
        }
        #pragma unroll
        for (int h = 0; h < NKV; h++) {
            float* x = row + (NH + h) * DHEAD;
            float x1 = x[tid], x2 = x[tid + 64];
            kout[h * DHEAD + tid]      = x1 * c - x2 * s;
            kout[h * DHEAD + tid + 64] = x2 * c + x1 * s;
        }
    }
    // v: straight copy into cache (all 128 threads)
    #pragma unroll
    for (int h = 0; h < NKV; h++) {
        vout[h * DHEAD + tid] = row[(NH + NKV + h) * DHEAD + tid];
    }
}

// ---------------------------------------------------------------------------
// Flash attention (fp32), causal, GQA.
// ---------------------------------------------------------------------------
struct AttnSmem {
    float Qs[64][129];
    float Ks[64][129];
    float Vs[64][129];
    float Sc[64][65];
    float rowm[64];
    float rowl[64];
    float rowscale[64];
};

__global__ void attn_kernel(const float* __restrict__ cache,
                            const int* __restrict__ slot_mapping) {
    extern __shared__ char smem_raw[];
    AttnSmem& sm = *reinterpret_cast<AttnSmem*>(smem_raw);

    constexpr int BQ = 64, BK = 64;
    const int qt = blockIdx.x;           // q tile index (0..15)
    const int bh = blockIdx.y;           // 0..111
    const int b  = bh / NH;
    const int h  = bh % NH;
    const int kv = h / GROUP;
    const int tid = threadIdx.x;         // 256

    for (int i = tid; i < BQ * DHEAD; i += 256) {
        const int r = i >> 7, d = i & 127;
        const int t = b * SEQ + qt * BQ + r;
        sm.Qs[r][d] = g_qkv[(size_t)t * QKV_OUT + h * DHEAD + d] * SCALE_F;
    }
    if (tid < BQ) { sm.rowm[tid] = NEG_BIG; sm.rowl[tid] = 0.f; }
    __syncthreads();

    const int rg = tid >> 4;
    const int cg = tid & 15;

    float Oacc[4][8];
    #pragma unroll
    for (int i = 0; i < 4; i++)
        #pragma unroll
        for (int j = 0; j < 8; j++) Oacc[i][j] = 0.f;

    const int nkt = qt + 1;
    for (int kt = 0; kt < nkt; kt++) {
        for (int i = tid; i < BK * DHEAD; i += 256) {
            const int r = i >> 7, d = i & 127;
            const int tk = b * SEQ + kt * BK + r;
            const int slot = slot_mapping[tk];
            const size_t base = (size_t)slot * NKV * DHEAD + kv * DHEAD + d;
            sm.Ks[r][d] = cache[base];
            sm.Vs[r][d] = cache[(size_t)NSLOTS * NKV * DHEAD + base];
        }
        __syncthreads();

        float s4[4][4];
        #pragma unroll
        for (int i = 0; i < 4; i++)
            #pragma unroll
            for (int j = 0; j < 4; j++) s4[i][j] = 0.f;

        #pragma unroll 4
        for (int d = 0; d < DHEAD; d++) {
            float qv[4], kr[4];
            #pragma unroll
            for (int i = 0; i < 4; i++) qv[i] = sm.Qs[rg * 4 + i][d];
            #pragma unroll
            for (int j = 0; j < 4; j++) kr[j] = sm.Ks[cg * 4 + j][d];
            #pragma unroll
            for (int i = 0; i < 4; i++)
                #pragma unroll
                for (int j = 0; j < 4; j++)
                    s4[i][j] += qv[i] * kr[j];
        }

        const bool diag = (kt == qt);
        #pragma unroll
        for (int i = 0; i < 4; i++) {
            const int r = rg * 4 + i;
            #pragma unroll
            for (int j = 0; j < 4; j++) {
                const int c = cg * 4 + j;
                float val = s4[i][j];
                if (diag && c > r) val = NEG_BIG;
                sm.Sc[r][c] = val;
            }
        }
        __syncthreads();

        if (tid < BQ) {
            const int r = tid;
            float m = sm.rowm[r];
            float mx = m;
            #pragma unroll 8
            for (int c = 0; c < BK; c++) mx = fmaxf(mx, sm.Sc[r][c]);
            const float sc = expf(m - mx);
            float l = sm.rowl[r] * sc;
            #pragma unroll 8
            for (int c = 0; c < BK; c++) {
                float p = expf(sm.Sc[r][c] - mx);
                sm.Sc[r][c] = p;
                l += p;
            }
            sm.rowm[r] = mx;
            sm.rowl[r] = l;
            sm.rowscale[r] = sc;
        }
        __syncthreads();

        float rs[4];
        #pragma unroll
        for (int i = 0; i < 4; i++) rs[i] = sm.rowscale[rg * 4 + i];
        #pragma unroll
        for (int i = 0; i < 4; i++)
            #pragma unroll
            for (int j = 0; j < 8; j++) Oacc[i][j] *= rs[i];

        #pragma unroll 2
        for (int c = 0; c < BK; c++) {
            float p[4], vv[8];
            #pragma unroll
            for (int i = 0; i < 4; i++) p[i] = sm.Sc[rg * 4 + i][c];
            #pragma unroll
            for (int j = 0; j < 8; j++) vv[j] = sm.Vs[c][cg * 8 + j];
            #pragma unroll
            for (int i = 0; i < 4; i++)
                #pragma unroll
                for (int j = 0; j < 8; j++)
                    Oacc[i][j] += p[i] * vv[j];
        }
        __syncthreads();
    }

    #pragma unroll
    for (int i = 0; i < 4; i++) {
        const int r = rg * 4 + i;
        const float invl = 1.f / sm.rowl[r];
        const int t = b * SEQ + qt * BQ + r;
        float* dst = g_ctx + (size_t)t * (NH * DHEAD) + h * DHEAD + cg * 8;
        #pragma unroll
        for (int j = 0; j < 8; j++) dst[j] = Oacc[i][j] * invl;
    }
}

// ---------------------------------------------------------------------------
// Launch
// ---------------------------------------------------------------------------
extern "C" void kernel_launch(void* const* d_in, const int* in_sizes, int n_in,
                              void* d_out, int out_size) {
    const int*   positions    = (const int*)  d_in[0];
    const float* hidden       = (const float*)d_in[1];
    const float* kv_cache_in  = (const float*)d_in[2];
    const int*   slot_mapping = (const int*)  d_in[4];
    const float* w_qkv = (const float*)d_in[n_in - 3];
    const float* b_qkv = (const float*)d_in[n_in - 2];
    const float* w_o   = (const float*)d_in[n_in - 1];

    float* out       = (float*)d_out;
    float* cache_out = out + (size_t)T_TOK * HDIM;

    float* qkv_ptr; cudaGetSymbolAddress((void**)&qkv_ptr, g_qkv);
    float* ctx_ptr; cudaGetSymbolAddress((void**)&ctx_ptr, g_ctx);

    // 1) Seed output cache with the input cache (untouched slots must match)
    cudaMemcpyAsync(cache_out, kv_cache_in,
                    (size_t)2 * NSLOTS * NKV * DHEAD * sizeof(float),
                    cudaMemcpyDeviceToDevice, 0);

    // 2) QKV projection
    {
        dim3 grid(QKV_OUT / 128, T_TOK / 128);
        sgemm_tn<<<grid, 256>>>(hidden, w_qkv, b_qkv, qkv_ptr,
                                T_TOK, QKV_OUT, HDIM);
    }

    // 3) RoPE + scatter into cache
    rope_scatter_kernel<<<T_TOK, 128>>>(positions, slot_mapping, cache_out);

    // 4) Causal GQA flash attention -> g_ctx
    {
        cudaFuncSetAttribute(attn_kernel,
                             cudaFuncAttributeMaxDynamicSharedMemorySize,
                             (int)sizeof(AttnSmem));
        dim3 grid(SEQ / 64, BATCH * NH);
        attn_kernel<<<grid, 256, sizeof(AttnSmem)>>>(cache_out, slot_mapping);
    }

    // 5) Output projection
    {
        dim3 grid(HDIM / 128, T_TOK / 128);
        sgemm_tn<<<grid, 256>>>(ctx_ptr, w_o, nullptr, out,
                                T_TOK, HDIM, NH * DHEAD);
    }
}

// round 6
// speedup vs baseline: 1.7735x; 1.7735x over previous
#include <cuda_runtime.h>
#include <cuda_bf16.h>
#include <math.h>
#include <stdint.h>

// ---------------------------------------------------------------------------
// Problem constants (Qwen2Attention_11725260718470)
// ---------------------------------------------------------------------------
#define T_TOK   4096
#define HDIM    3584
#define NH      28
#define NKV     4
#define DHEAD   128
#define GROUP   7
#define BATCH   4
#define SEQ     1024
#define QKV_OUT 4608
#define NSLOTS  8192
#define SCALE_F 0.08838834764831845f
#define NEG_BIG (-1e30f)

// ---------------------------------------------------------------------------
// Device scratch
// ---------------------------------------------------------------------------
__device__ float g_qkv[(size_t)T_TOK * QKV_OUT];
__device__ float g_ctx[(size_t)T_TOK * NH * DHEAD];

__device__ __nv_bfloat16 g_hid_hi[(size_t)T_TOK * HDIM];
__device__ __nv_bfloat16 g_hid_lo[(size_t)T_TOK * HDIM];
__device__ __nv_bfloat16 g_wqkv_hi[(size_t)QKV_OUT * HDIM];
__device__ __nv_bfloat16 g_wqkv_lo[(size_t)QKV_OUT * HDIM];
__device__ __nv_bfloat16 g_wo_hi[(size_t)HDIM * HDIM];
__device__ __nv_bfloat16 g_wo_lo[(size_t)HDIM * HDIM];
__device__ __nv_bfloat16 g_ctx_hi[(size_t)T_TOK * HDIM];
__device__ __nv_bfloat16 g_ctx_lo[(size_t)T_TOK * HDIM];

// ---------------------------------------------------------------------------
// Baseline-PTX helpers (ldmatrix / mma.sync / cp.async — NOT arch-specific)
// ---------------------------------------------------------------------------
__device__ __forceinline__ uint32_t smem_u32(const void* p) {
    uint32_t a;
    asm("{ .reg .u64 t; cvta.to.shared.u64 t, %1; cvt.u32.u64 %0, t; }"
        : "=r"(a) : "l"(p));
    return a;
}
__device__ __forceinline__ void cp_async16(uint32_t dst, const void* src) {
    asm volatile("cp.async.cg.shared.global [%0], [%1], 16;"
                 :: "r"(dst), "l"(src));
}
__device__ __forceinline__ void cp_commit() {
    asm volatile("cp.async.commit_group;");
}
__device__ __forceinline__ void ldmx4(uint32_t* r, uint32_t addr) {
    asm volatile("ldmatrix.sync.aligned.m8n8.x4.shared.b16 {%0,%1,%2,%3}, [%4];"
                 : "=r"(r[0]), "=r"(r[1]), "=r"(r[2]), "=r"(r[3]) : "r"(addr));
}
__device__ __forceinline__ void ldmx2(uint32_t* r, uint32_t addr) {
    asm volatile("ldmatrix.sync.aligned.m8n8.x2.shared.b16 {%0,%1}, [%2];"
                 : "=r"(r[0]), "=r"(r[1]) : "r"(addr));
}
__device__ __forceinline__ void mma16816(float* c, const uint32_t* a, const uint32_t* b) {
    asm volatile(
        "mma.sync.aligned.m16n8k16.row.col.f32.bf16.bf16.f32 "
        "{%0,%1,%2,%3}, {%4,%5,%6,%7}, {%8,%9}, {%0,%1,%2,%3};"
        : "+f"(c[0]), "+f"(c[1]), "+f"(c[2]), "+f"(c[3])
        : "r"(a[0]), "r"(a[1]), "r"(a[2]), "r"(a[3]), "r"(b[0]), "r"(b[1]));
}

// ---------------------------------------------------------------------------
// Split fp32 -> bf16 hi/lo (hi = bf16(x), lo = bf16(x - hi))
// ---------------------------------------------------------------------------
__device__ __forceinline__ uint32_t pack_bf2(__nv_bfloat16 a, __nv_bfloat16 b) {
    return (uint32_t)__bfloat16_as_ushort(a) | ((uint32_t)__bfloat16_as_ushort(b) << 16);
}
__global__ void split_f32_bf16(const float4* __restrict__ x,
                               uint2* __restrict__ hi, uint2* __restrict__ lo, int n4) {
    int i = blockIdx.x * blockDim.x + threadIdx.x;
    if (i >= n4) return;
    float4 v = x[i];
    __nv_bfloat16 h0 = __float2bfloat16(v.x);
    __nv_bfloat16 h1 = __float2bfloat16(v.y);
    __nv_bfloat16 h2 = __float2bfloat16(v.z);
    __nv_bfloat16 h3 = __float2bfloat16(v.w);
    __nv_bfloat16 l0 = __float2bfloat16(v.x - __bfloat162float(h0));
    __nv_bfloat16 l1 = __float2bfloat16(v.y - __bfloat162float(h1));
    __nv_bfloat16 l2 = __float2bfloat16(v.z - __bfloat162float(h2));
    __nv_bfloat16 l3 = __float2bfloat16(v.w - __bfloat162float(h3));
    uint2 hv, lv;
    hv.x = pack_bf2(h0, h1); hv.y = pack_bf2(h2, h3);
    lv.x = pack_bf2(l0, l1); lv.y = pack_bf2(l2, l3);
    hi[i] = hv;
    lo[i] = lv;
}

// ---------------------------------------------------------------------------
// bf16x3 split-precision GEMM on mma.sync (legacy tensor-core path).
// C[m,n] = sum_k A[m,k]*B[n,k] (+bias[n]);  A:[M,K], B:[N,K] row-major bf16.
// Tile 128x128x32, 8 warps (2x4), cp.async double-buffered, fp32 accum.
// SMEM rows padded: 32 bf16 (64B) stored at 80B stride -> ldmatrix is
// bank-conflict-free (row starts 0,20,8,28,16,4,24,12 banks).
// ---------------------------------------------------------------------------
#define GBK        32
#define ROW_B      80                       // padded row bytes
#define TILE_B     (128 * ROW_B)            // 10240
#define STAGE_B    (4 * TILE_B)             // Ahi, Alo, Bhi, Blo = 40960
#define GSMEM_BYTES (2 * STAGE_B)           // 81920

__global__ __launch_bounds__(256, 1)
void gemm_bf16x3(const __nv_bfloat16* __restrict__ Ahi, const __nv_bfloat16* __restrict__ Alo,
                 const __nv_bfloat16* __restrict__ Bhi, const __nv_bfloat16* __restrict__ Blo,
                 const float* __restrict__ bias, float* __restrict__ C,
                 int M, int N, int K) {
    extern __shared__ char smem[];
    const uint32_t sbase = smem_u32(smem);

    const int tid  = threadIdx.x;
    const int wid  = tid >> 5;
    const int lane = tid & 31;
    const int bm = blockIdx.y * 128;
    const int bn = blockIdx.x * 128;
    const int warp_m = (wid >> 2) * 64;     // 0 or 64
    const int warp_n = (wid & 3) * 32;      // 0,32,64,96

    const __nv_bfloat16* gsrc[4] = {
        Ahi + (size_t)bm * K, Alo + (size_t)bm * K,
        Bhi + (size_t)bn * K, Blo + (size_t)bn * K };

    const int NS = K / GBK;

    // per-thread load slots: 2048 chunks/stage, 8 per thread
    // chunk within tile: idx = tid + i*256 (i=0,1): row = idx>>2, cc = idx&3
    auto load_stage = [&](int buf, int k0) {
        const uint32_t sb = sbase + buf * STAGE_B;
        #pragma unroll
        for (int t = 0; t < 4; t++) {
            const __nv_bfloat16* g = gsrc[t] + k0;
            #pragma unroll
            for (int i = 0; i < 2; i++) {
                int idx = tid + i * 256;
                int row = idx >> 2;
                int cc  = idx & 3;
                cp_async16(sb + t * TILE_B + row * ROW_B + cc * 16,
                           g + (size_t)row * K + cc * 8);
            }
        }
        cp_commit();
    };

    float acc[4][4][4];
    #pragma unroll
    for (int mt = 0; mt < 4; mt++)
        #pragma unroll
        for (int nt = 0; nt < 4; nt++)
            #pragma unroll
            for (int j = 0; j < 4; j++) acc[mt][nt][j] = 0.f;

    load_stage(0, 0);

    // ldmatrix lane addressing (constant per thread)
    const int a_row  = warp_m + ((lane >> 3) & 1) * 8 + (lane & 7);
    const int a_koff = ((lane >> 4) & 1) * 16;        // +16B for k8..15 matrices
    const int l2     = lane & 15;
    const int b_row  = warp_n + (l2 & 7);
    const int b_koff = ((l2 >> 3) & 1) * 16;

    for (int s = 0; s < NS; s++) {
        if (s + 1 < NS) {
            load_stage((s + 1) & 1, (s + 1) * GBK);
            asm volatile("cp.async.wait_group 1;");
        } else {
            asm volatile("cp.async.wait_group 0;");
        }
        __syncthreads();

        const uint32_t sb  = sbase + (s & 1) * STAGE_B;
        const uint32_t aH = sb + 0 * TILE_B;
        const uint32_t aL = sb + 1 * TILE_B;
        const uint32_t bH = sb + 2 * TILE_B;
        const uint32_t bL = sb + 3 * TILE_B;

        #pragma unroll
        for (int ks = 0; ks < 2; ks++) {
            const int kb = ks * 32;   // byte offset of k-step within 64B row
            uint32_t ah[4][4], al[4][4], bh[4][2], bl[4][2];
            #pragma unroll
            for (int mt = 0; mt < 4; mt++) {
                uint32_t off = (uint32_t)(a_row + mt * 16) * ROW_B + kb + a_koff;
                ldmx4(ah[mt], aH + off);
                ldmx4(al[mt], aL + off);
            }
            #pragma unroll
            for (int nt = 0; nt < 4; nt++) {
                uint32_t off = (uint32_t)(b_row + nt * 8) * ROW_B + kb + b_koff;
                ldmx2(bh[nt], bH + off);
                ldmx2(bl[nt], bL + off);
            }
            #pragma unroll
            for (int mt = 0; mt < 4; mt++)
                #pragma unroll
                for (int nt = 0; nt < 4; nt++) {
                    mma16816(acc[mt][nt], ah[mt], bh[nt]);
                    mma16816(acc[mt][nt], ah[mt], bl[nt]);
                    mma16816(acc[mt][nt], al[mt], bh[nt]);
                }
        }
        __syncthreads();
    }

    // Epilogue: c0,c1 -> (row = lane/4, col = (lane%4)*2), c2,c3 -> row+8
    #pragma unroll
    for (int mt = 0; mt < 4; mt++) {
        #pragma unroll
        for (int nt = 0; nt < 4; nt++) {
            const int r0 = bm + warp_m + mt * 16 + (lane >> 2);
            const int cl = bn + warp_n + nt * 8 + (lane & 3) * 2;
            const float b0 = bias ? bias[cl]     : 0.f;
            const float b1 = bias ? bias[cl + 1] : 0.f;
            float2 v0 = make_float2(acc[mt][nt][0] + b0, acc[mt][nt][1] + b1);
            float2 v1 = make_float2(acc[mt][nt][2] + b0, acc[mt][nt][3] + b1);
            *(float2*)(C + (size_t)r0 * N + cl)       = v0;
            *(float2*)(C + (size_t)(r0 + 8) * N + cl) = v1;
        }
    }
}

// ---------------------------------------------------------------------------
// RoPE + cache scatter (validated in R2)
// ---------------------------------------------------------------------------
__global__ void rope_scatter_kernel(const int* __restrict__ positions,
                                    const int* __restrict__ slot_mapping,
                                    float* __restrict__ cache_out) {
    const int t = blockIdx.x;
    const int tid = threadIdx.x;
    const int pos = positions[t];
    float* row = g_qkv + (size_t)t * QKV_OUT;
    const int slot = slot_mapping[t];
    float* kout = cache_out + (size_t)slot * NKV * DHEAD;
    float* vout = cache_out + (size_t)NSLOTS * NKV * DHEAD + (size_t)slot * NKV * DHEAD;

    if (tid < 64) {
        const float invf = expf(-(float)tid * (logf(10000.f) / 64.f));
        const double ang = (double)pos * (double)invf;
        double dc, ds;
        sincos(ang, &ds, &dc);
        const float c = (float)dc;
        const float s = (float)ds;

        #pragma unroll 4
        for (int h = 0; h < NH; h++) {
            float* x = row + h * DHEAD;
            float x1 = x[tid], x2 = x[tid + 64];
            x[tid]      = x1 * c - x2 * s;
            x[tid + 64] = x2 * c + x1 * s;
        }
        #pragma unroll
        for (int h = 0; h < NKV; h++) {
            float* x = row + (NH + h) * DHEAD;
            float x1 = x[tid], x2 = x[tid + 64];
            kout[h * DHEAD + tid]      = x1 * c - x2 * s;
            kout[h * DHEAD + tid + 64] = x2 * c + x1 * s;
        }
    }
    #pragma unroll
    for (int h = 0; h < NKV; h++) {
        vout[h * DHEAD + tid] = row[(NH + NKV + h) * DHEAD + tid];
    }
}

// ---------------------------------------------------------------------------
// Flash attention (fp32, validated in R2)
// ---------------------------------------------------------------------------
struct AttnSmem {
    float Qs[64][129];
    float Ks[64][129];
    float Vs[64][129];
    float Sc[64][65];
    float rowm[64];
    float rowl[64];
    float rowscale[64];
};

__global__ void attn_kernel(const float* __restrict__ cache,
                            const int* __restrict__ slot_mapping) {
    extern __shared__ char smem_raw[];
    AttnSmem& sm = *reinterpret_cast<AttnSmem*>(smem_raw);

    constexpr int BQ = 64, BK = 64;
    const int qt = blockIdx.x;
    const int bh = blockIdx.y;
    const int b  = bh / NH;
    const int h  = bh % NH;
    const int kv = h / GROUP;
    const int tid = threadIdx.x;

    for (int i = tid; i < BQ * DHEAD; i += 256) {
        const int r = i >> 7, d = i & 127;
        const int t = b * SEQ + qt * BQ + r;
        sm.Qs[r][d] = g_qkv[(size_t)t * QKV_OUT + h * DHEAD + d] * SCALE_F;
    }
    if (tid < BQ) { sm.rowm[tid] = NEG_BIG; sm.rowl[tid] = 0.f; }
    __syncthreads();

    const int rg = tid >> 4;
    const int cg = tid & 15;

    float Oacc[4][8];
    #pragma unroll
    for (int i = 0; i < 4; i++)
        #pragma unroll
        for (int j = 0; j < 8; j++) Oacc[i][j] = 0.f;

    const int nkt = qt + 1;
    for (int kt = 0; kt < nkt; kt++) {
        for (int i = tid; i < BK * DHEAD; i += 256) {
            const int r = i >> 7, d = i & 127;
            const int tk = b * SEQ + kt * BK + r;
            const int slot = slot_mapping[tk];
            const size_t base = (size_t)slot * NKV * DHEAD + kv * DHEAD + d;
            sm.Ks[r][d] = cache[base];
            sm.Vs[r][d] = cache[(size_t)NSLOTS * NKV * DHEAD + base];
        }
        __syncthreads();

        float s4[4][4];
        #pragma unroll
        for (int i = 0; i < 4; i++)
            #pragma unroll
            for (int j = 0; j < 4; j++) s4[i][j] = 0.f;

        #pragma unroll 4
        for (int d = 0; d < DHEAD; d++) {
            float qv[4], kr[4];
            #pragma unroll
            for (int i = 0; i < 4; i++) qv[i] = sm.Qs[rg * 4 + i][d];
            #pragma unroll
            for (int j = 0; j < 4; j++) kr[j] = sm.Ks[cg * 4 + j][d];
            #pragma unroll
            for (int i = 0; i < 4; i++)
                #pragma unroll
                for (int j = 0; j < 4; j++)
                    s4[i][j] += qv[i] * kr[j];
        }

        const bool diag = (kt == qt);
        #pragma unroll
        for (int i = 0; i < 4; i++) {
            const int r = rg * 4 + i;
            #pragma unroll
            for (int j = 0; j < 4; j++) {
                const int c = cg * 4 + j;
                float val = s4[i][j];
                if (diag && c > r) val = NEG_BIG;
                sm.Sc[r][c] = val;
            }
        }
        __syncthreads();

        if (tid < BQ) {
            const int r = tid;
            float m = sm.rowm[r];
            float mx = m;
            #pragma unroll 8
            for (int c = 0; c < BK; c++) mx = fmaxf(mx, sm.Sc[r][c]);
            const float sc = expf(m - mx);
            float l = sm.rowl[r] * sc;
            #pragma unroll 8
            for (int c = 0; c < BK; c++) {
                float p = expf(sm.Sc[r][c] - mx);
                sm.Sc[r][c] = p;
                l += p;
            }
            sm.rowm[r] = mx;
            sm.rowl[r] = l;
            sm.rowscale[r] = sc;
        }
        __syncthreads();

        float rs[4];
        #pragma unroll
        for (int i = 0; i < 4; i++) rs[i] = sm.rowscale[rg * 4 + i];
        #pragma unroll
        for (int i = 0; i < 4; i++)
            #pragma unroll
            for (int j = 0; j < 8; j++) Oacc[i][j] *= rs[i];

        #pragma unroll 2
        for (int c = 0; c < BK; c++) {
            float p[4], vv[8];
            #pragma unroll
            for (int i = 0; i < 4; i++) p[i] = sm.Sc[rg * 4 + i][c];
            #pragma unroll
            for (int j = 0; j < 8; j++) vv[j] = sm.Vs[c][cg * 8 + j];
            #pragma unroll
            for (int i = 0; i < 4; i++)
                #pragma unroll
                for (int j = 0; j < 8; j++)
                    Oacc[i][j] += p[i] * vv[j];
        }
        __syncthreads();
    }

    #pragma unroll
    for (int i = 0; i < 4; i++) {
        const int r = rg * 4 + i;
        const float invl = 1.f / sm.rowl[r];
        const int t = b * SEQ + qt * BQ + r;
        float* dst = g_ctx + (size_t)t * (NH * DHEAD) + h * DHEAD + cg * 8;
        #pragma unroll
        for (int j = 0; j < 8; j++) dst[j] = Oacc[i][j] * invl;
    }
}

// ---------------------------------------------------------------------------
// Launch
// ---------------------------------------------------------------------------
extern "C" void kernel_launch(void* const* d_in, const int* in_sizes, int n_in,
                              void* d_out, int out_size) {
    const int*   positions    = (const int*)  d_in[0];
    const float* hidden       = (const float*)d_in[1];
    const float* kv_cache_in  = (const float*)d_in[2];
    const int*   slot_mapping = (const int*)  d_in[4];
    const float* w_qkv = (const float*)d_in[n_in - 3];
    const float* b_qkv = (const float*)d_in[n_in - 2];
    const float* w_o   = (const float*)d_in[n_in - 1];

    float* out       = (float*)d_out;
    float* cache_out = out + (size_t)T_TOK * HDIM;

    float* qkv_ptr; cudaGetSymbolAddress((void**)&qkv_ptr, g_qkv);
    float* ctx_ptr; cudaGetSymbolAddress((void**)&ctx_ptr, g_ctx);
    __nv_bfloat16 *hid_hi, *hid_lo, *wqkv_hi, *wqkv_lo, *wo_hi, *wo_lo, *ctx_hi, *ctx_lo;
    cudaGetSymbolAddress((void**)&hid_hi,  g_hid_hi);
    cudaGetSymbolAddress((void**)&hid_lo,  g_hid_lo);
    cudaGetSymbolAddress((void**)&wqkv_hi, g_wqkv_hi);
    cudaGetSymbolAddress((void**)&wqkv_lo, g_wqkv_lo);
    cudaGetSymbolAddress((void**)&wo_hi,   g_wo_hi);
    cudaGetSymbolAddress((void**)&wo_lo,   g_wo_lo);
    cudaGetSymbolAddress((void**)&ctx_hi,  g_ctx_hi);
    cudaGetSymbolAddress((void**)&ctx_lo,  g_ctx_lo);

    cudaFuncSetAttribute(attn_kernel,
                         cudaFuncAttributeMaxDynamicSharedMemorySize,
                         (int)sizeof(AttnSmem));
    cudaFuncSetAttribute(gemm_bf16x3,
                         cudaFuncAttributeMaxDynamicSharedMemorySize,
                         GSMEM_BYTES);

    // 1) Seed output cache with the input cache
    cudaMemcpyAsync(cache_out, kv_cache_in,
                    (size_t)2 * NSLOTS * NKV * DHEAD * sizeof(float),
                    cudaMemcpyDeviceToDevice, 0);

    // 2) Split hidden + w_qkv + w_o into bf16 hi/lo
    {
        int n4 = (T_TOK * HDIM) / 4;
        split_f32_bf16<<<(n4 + 255) / 256, 256>>>((const float4*)hidden,
                                                  (uint2*)hid_hi, (uint2*)hid_lo, n4);
        n4 = (QKV_OUT * HDIM) / 4;
        split_f32_bf16<<<(n4 + 255) / 256, 256>>>((const float4*)w_qkv,
                                                  (uint2*)wqkv_hi, (uint2*)wqkv_lo, n4);
        n4 = (HDIM * HDIM) / 4;
        split_f32_bf16<<<(n4 + 255) / 256, 256>>>((const float4*)w_o,
                                                  (uint2*)wo_hi, (uint2*)wo_lo, n4);
    }

    // 3) QKV projection on tensor cores (mma.sync bf16x3)
    {
        dim3 grid(QKV_OUT / 128, T_TOK / 128);
        gemm_bf16x3<<<grid, 256, GSMEM_BYTES>>>(hid_hi, hid_lo, wqkv_hi, wqkv_lo,
                                                b_qkv, qkv_ptr,
                                                T_TOK, QKV_OUT, HDIM);
    }

    // 4) RoPE + cache scatter
    rope_scatter_kernel<<<T_TOK, 128>>>(positions, slot_mapping, cache_out);

    // 5) Causal GQA flash attention -> g_ctx
    {
        dim3 grid(SEQ / 64, BATCH * NH);
        attn_kernel<<<grid, 256, sizeof(AttnSmem)>>>(cache_out, slot_mapping);
    }

    // 6) Split ctx into bf16 hi/lo
    {
        int n4 = (T_TOK * HDIM) / 4;
        split_f32_bf16<<<(n4 + 255) / 256, 256>>>((const float4*)ctx_ptr,
                                                  (uint2*)ctx_hi, (uint2*)ctx_lo, n4);
    }

    // 7) Output projection on tensor cores
    {
        dim3 grid(HDIM / 128, T_TOK / 128);
        gemm_bf16x3<<<grid, 256, GSMEM_BYTES>>>(ctx_hi, ctx_lo, wo_hi, wo_lo,
                                                nullptr, out,
                                                T_TOK, HDIM, NH * DHEAD);
    }
}

// round 8
// speedup vs baseline: 3.0168x; 1.7010x over previous
#include <cuda_runtime.h>
#include <cuda_bf16.h>
#include <math.h>
#include <stdint.h>

// ---------------------------------------------------------------------------
// Problem constants (Qwen2Attention_11725260718470)
// ---------------------------------------------------------------------------
#define T_TOK   4096
#define HDIM    3584
#define NH      28
#define NKV     4
#define DHEAD   128
#define GROUP   7
#define BATCH   4
#define SEQ     1024
#define QKV_OUT 4608
#define NSLOTS  8192
#define SCALE_F 0.08838834764831845f
#define NEG_BIG (-1e30f)

// ---------------------------------------------------------------------------
// Device scratch
// ---------------------------------------------------------------------------
__device__ float g_qkv[(size_t)T_TOK * QKV_OUT];

__device__ __nv_bfloat16 g_hid_hi[(size_t)T_TOK * HDIM];
__device__ __nv_bfloat16 g_hid_lo[(size_t)T_TOK * HDIM];
__device__ __nv_bfloat16 g_wqkv_hi[(size_t)QKV_OUT * HDIM];
__device__ __nv_bfloat16 g_wqkv_lo[(size_t)QKV_OUT * HDIM];
__device__ __nv_bfloat16 g_wo_hi[(size_t)HDIM * HDIM];
__device__ __nv_bfloat16 g_wo_lo[(size_t)HDIM * HDIM];
__device__ __nv_bfloat16 g_ctx_hi[(size_t)T_TOK * HDIM];
__device__ __nv_bfloat16 g_ctx_lo[(size_t)T_TOK * HDIM];

// bf16 mirrors for attention (written by rope kernel)
__device__ __nv_bfloat16 g_qb [(size_t)T_TOK * NH * DHEAD];   // roped, pre-scaled
__device__ __nv_bfloat16 g_kb [(size_t)T_TOK * NKV * DHEAD];  // roped
__device__ __nv_bfloat16 g_vhb[(size_t)T_TOK * NKV * DHEAD];  // v hi
__device__ __nv_bfloat16 g_vlb[(size_t)T_TOK * NKV * DHEAD];  // v lo

// ---------------------------------------------------------------------------
// Baseline-PTX helpers (ldmatrix / mma.sync / cp.async — NOT arch-specific)
// ---------------------------------------------------------------------------
__device__ __forceinline__ uint32_t smem_u32(const void* p) {
    uint32_t a;
    asm("{ .reg .u64 t; cvta.to.shared.u64 t, %1; cvt.u32.u64 %0, t; }"
        : "=r"(a) : "l"(p));
    return a;
}
__device__ __forceinline__ void cp_async16(uint32_t dst, const void* src) {
    asm volatile("cp.async.cg.shared.global [%0], [%1], 16;"
                 :: "r"(dst), "l"(src));
}
__device__ __forceinline__ void cp_commit() {
    asm volatile("cp.async.commit_group;");
}
__device__ __forceinline__ void ldmx4(uint32_t* r, uint32_t addr) {
    asm volatile("ldmatrix.sync.aligned.m8n8.x4.shared.b16 {%0,%1,%2,%3}, [%4];"
                 : "=r"(r[0]), "=r"(r[1]), "=r"(r[2]), "=r"(r[3]) : "r"(addr));
}
__device__ __forceinline__ void ldmx2(uint32_t* r, uint32_t addr) {
    asm volatile("ldmatrix.sync.aligned.m8n8.x2.shared.b16 {%0,%1}, [%2];"
                 : "=r"(r[0]), "=r"(r[1]) : "r"(addr));
}
__device__ __forceinline__ void ldmx2t(uint32_t* r, uint32_t addr) {
    asm volatile("ldmatrix.sync.aligned.m8n8.x2.trans.shared.b16 {%0,%1}, [%2];"
                 : "=r"(r[0]), "=r"(r[1]) : "r"(addr));
}
__device__ __forceinline__ void mma16816(float* c, const uint32_t* a, const uint32_t* b) {
    asm volatile(
        "mma.sync.aligned.m16n8k16.row.col.f32.bf16.bf16.f32 "
        "{%0,%1,%2,%3}, {%4,%5,%6,%7}, {%8,%9}, {%0,%1,%2,%3};"
        : "+f"(c[0]), "+f"(c[1]), "+f"(c[2]), "+f"(c[3])
        : "r"(a[0]), "r"(a[1]), "r"(a[2]), "r"(a[3]), "r"(b[0]), "r"(b[1]));
}

// ---------------------------------------------------------------------------
// Split fp32 -> bf16 hi/lo
// ---------------------------------------------------------------------------
__device__ __forceinline__ uint32_t pack_bf2(__nv_bfloat16 a, __nv_bfloat16 b) {
    return (uint32_t)__bfloat16_as_ushort(a) | ((uint32_t)__bfloat16_as_ushort(b) << 16);
}
__global__ void split_f32_bf16(const float4* __restrict__ x,
                               uint2* __restrict__ hi, uint2* __restrict__ lo, int n4) {
    int i = blockIdx.x * blockDim.x + threadIdx.x;
    if (i >= n4) return;
    float4 v = x[i];
    __nv_bfloat16 h0 = __float2bfloat16(v.x);
    __nv_bfloat16 h1 = __float2bfloat16(v.y);
    __nv_bfloat16 h2 = __float2bfloat16(v.z);
    __nv_bfloat16 h3 = __float2bfloat16(v.w);
    __nv_bfloat16 l0 = __float2bfloat16(v.x - __bfloat162float(h0));
    __nv_bfloat16 l1 = __float2bfloat16(v.y - __bfloat162float(h1));
    __nv_bfloat16 l2 = __float2bfloat16(v.z - __bfloat162float(h2));
    __nv_bfloat16 l3 = __float2bfloat16(v.w - __bfloat162float(h3));
    uint2 hv, lv;
    hv.x = pack_bf2(h0, h1); hv.y = pack_bf2(h2, h3);
    lv.x = pack_bf2(l0, l1); lv.y = pack_bf2(l2, l3);
    hi[i] = hv;
    lo[i] = lv;
}

// ---------------------------------------------------------------------------
// bf16x3 split-precision GEMM on mma.sync (validated in R6, unchanged)
// ---------------------------------------------------------------------------
#define GBK        32
#define ROW_B      80
#define TILE_B     (128 * ROW_B)
#define STAGE_B    (4 * TILE_B)
#define GSMEM_BYTES (2 * STAGE_B)

__global__ __launch_bounds__(256, 1)
void gemm_bf16x3(const __nv_bfloat16* __restrict__ Ahi, const __nv_bfloat16* __restrict__ Alo,
                 const __nv_bfloat16* __restrict__ Bhi, const __nv_bfloat16* __restrict__ Blo,
                 const float* __restrict__ bias, float* __restrict__ C,
                 int M, int N, int K) {
    extern __shared__ char smem[];
    const uint32_t sbase = smem_u32(smem);

    const int tid  = threadIdx.x;
    const int wid  = tid >> 5;
    const int lane = tid & 31;
    const int bm = blockIdx.y * 128;
    const int bn = blockIdx.x * 128;
    const int warp_m = (wid >> 2) * 64;
    const int warp_n = (wid & 3) * 32;

    const __nv_bfloat16* gsrc[4] = {
        Ahi + (size_t)bm * K, Alo + (size_t)bm * K,
        Bhi + (size_t)bn * K, Blo + (size_t)bn * K };

    const int NS = K / GBK;

    auto load_stage = [&](int buf, int k0) {
        const uint32_t sb = sbase + buf * STAGE_B;
        #pragma unroll
        for (int t = 0; t < 4; t++) {
            const __nv_bfloat16* g = gsrc[t] + k0;
            #pragma unroll
            for (int i = 0; i < 2; i++) {
                int idx = tid + i * 256;
                int row = idx >> 2;
                int cc  = idx & 3;
                cp_async16(sb + t * TILE_B + row * ROW_B + cc * 16,
                           g + (size_t)row * K + cc * 8);
            }
        }
        cp_commit();
    };

    float acc[4][4][4];
    #pragma unroll
    for (int mt = 0; mt < 4; mt++)
        #pragma unroll
        for (int nt = 0; nt < 4; nt++)
            #pragma unroll
            for (int j = 0; j < 4; j++) acc[mt][nt][j] = 0.f;

    load_stage(0, 0);

    const int a_row  = warp_m + ((lane >> 3) & 1) * 8 + (lane & 7);
    const int a_koff = ((lane >> 4) & 1) * 16;
    const int l2     = lane & 15;
    const int b_row  = warp_n + (l2 & 7);
    const int b_koff = ((l2 >> 3) & 1) * 16;

    for (int s = 0; s < NS; s++) {
        if (s + 1 < NS) {
            load_stage((s + 1) & 1, (s + 1) * GBK);
            asm volatile("cp.async.wait_group 1;");
        } else {
            asm volatile("cp.async.wait_group 0;");
        }
        __syncthreads();

        const uint32_t sb  = sbase + (s & 1) * STAGE_B;
        const uint32_t aH = sb + 0 * TILE_B;
        const uint32_t aL = sb + 1 * TILE_B;
        const uint32_t bH = sb + 2 * TILE_B;
        const uint32_t bL = sb + 3 * TILE_B;

        #pragma unroll
        for (int ks = 0; ks < 2; ks++) {
            const int kb = ks * 32;
            uint32_t ah[4][4], al[4][4], bh[4][2], bl[4][2];
            #pragma unroll
            for (int mt = 0; mt < 4; mt++) {
                uint32_t off = (uint32_t)(a_row + mt * 16) * ROW_B + kb + a_koff;
                ldmx4(ah[mt], aH + off);
                ldmx4(al[mt], aL + off);
            }
            #pragma unroll
            for (int nt = 0; nt < 4; nt++) {
                uint32_t off = (uint32_t)(b_row + nt * 8) * ROW_B + kb + b_koff;
                ldmx2(bh[nt], bH + off);
                ldmx2(bl[nt], bL + off);
            }
            #pragma unroll
            for (int mt = 0; mt < 4; mt++)
                #pragma unroll
                for (int nt = 0; nt < 4; nt++) {
                    mma16816(acc[mt][nt], ah[mt], bh[nt]);
                    mma16816(acc[mt][nt], ah[mt], bl[nt]);
                    mma16816(acc[mt][nt], al[mt], bh[nt]);
                }
        }
        __syncthreads();
    }

    #pragma unroll
    for (int mt = 0; mt < 4; mt++) {
        #pragma unroll
        for (int nt = 0; nt < 4; nt++) {
            const int r0 = bm + warp_m + mt * 16 + (lane >> 2);
            const int cl = bn + warp_n + nt * 8 + (lane & 3) * 2;
            const float b0 = bias ? bias[cl]     : 0.f;
            const float b1 = bias ? bias[cl + 1] : 0.f;
            float2 v0 = make_float2(acc[mt][nt][0] + b0, acc[mt][nt][1] + b1);
            float2 v1 = make_float2(acc[mt][nt][2] + b0, acc[mt][nt][3] + b1);
            *(float2*)(C + (size_t)r0 * N + cl)       = v0;
            *(float2*)(C + (size_t)(r0 + 8) * N + cl) = v1;
        }
    }
}

// ---------------------------------------------------------------------------
// RoPE + cache scatter + bf16 mirrors for attention
// ---------------------------------------------------------------------------
__global__ void rope_scatter_kernel(const int* __restrict__ positions,
                                    const int* __restrict__ slot_mapping,
                                    float* __restrict__ cache_out) {
    const int t = blockIdx.x;
    const int tid = threadIdx.x;
    const int pos = positions[t];
    float* row = g_qkv + (size_t)t * QKV_OUT;
    const int slot = slot_mapping[t];
    float* kout = cache_out + (size_t)slot * NKV * DHEAD;
    float* vout = cache_out + (size_t)NSLOTS * NKV * DHEAD + (size_t)slot * NKV * DHEAD;

    if (tid < 64) {
        const float invf = expf(-(float)tid * (logf(10000.f) / 64.f));
        const double ang = (double)pos * (double)invf;
        double dc, ds;
        sincos(ang, &ds, &dc);
        const float c = (float)dc;
        const float s = (float)ds;

        #pragma unroll 4
        for (int h = 0; h < NH; h++) {
            float* x = row + h * DHEAD;
            float x1 = x[tid], x2 = x[tid + 64];
            float r1 = x1 * c - x2 * s;
            float r2 = x2 * c + x1 * s;
            __nv_bfloat16* q = g_qb + ((size_t)t * NH + h) * DHEAD;
            q[tid]      = __float2bfloat16(r1 * SCALE_F);
            q[tid + 64] = __float2bfloat16(r2 * SCALE_F);
        }
        #pragma unroll
        for (int h = 0; h < NKV; h++) {
            float* x = row + (NH + h) * DHEAD;
            float x1 = x[tid], x2 = x[tid + 64];
            float r1 = x1 * c - x2 * s;
            float r2 = x2 * c + x1 * s;
            kout[h * DHEAD + tid]      = r1;
            kout[h * DHEAD + tid + 64] = r2;
            __nv_bfloat16* kb = g_kb + ((size_t)t * NKV + h) * DHEAD;
            kb[tid]      = __float2bfloat16(r1);
            kb[tid + 64] = __float2bfloat16(r2);
        }
    }
    #pragma unroll
    for (int h = 0; h < NKV; h++) {
        float v = row[(NH + NKV + h) * DHEAD + tid];
        vout[h * DHEAD + tid] = v;
        __nv_bfloat16 vh = __float2bfloat16(v);
        const size_t o = ((size_t)t * NKV + h) * DHEAD + tid;
        g_vhb[o] = vh;
        g_vlb[o] = __float2bfloat16(v - __bfloat162float(vh));
    }
}

// ---------------------------------------------------------------------------
// Tensor-core flash attention (FA2-style), causal, GQA.
// Block = (q-tile 64 rows, one head). 4 warps x 16 q-rows.
// QK^T: bf16 mma; softmax in fp32 regs; P,V split hi/lo (3 mma terms).
// Writes ctx_hi/ctx_lo bf16 directly for the O-projection.
// ---------------------------------------------------------------------------
#define ATT_STRIDE 272                 // 256B row + 16B pad (conflict-free)
#define ATT_TILE_B (64 * ATT_STRIDE)   // 17408
#define ATT_SMEM   (4 * ATT_TILE_B)    // Q, K, Vh, Vl = 69632

__global__ __launch_bounds__(128)
void attn_mma(const int* __restrict__ dummy) {
    extern __shared__ char smraw[];
    const uint32_t sb = smem_u32(smraw);
    const uint32_t Qs  = sb;
    const uint32_t Ks  = sb + ATT_TILE_B;
    const uint32_t Vhs = sb + 2 * ATT_TILE_B;
    const uint32_t Vls = sb + 3 * ATT_TILE_B;

    const int qt = blockIdx.x;          // 0..15
    const int bh = blockIdx.y;          // 0..111
    const int b  = bh / NH;
    const int h  = bh % NH;
    const int kv = h / GROUP;
    const int tid  = threadIdx.x;
    const int wid  = tid >> 5;
    const int lane = tid & 31;

    // ---- prologue loads: Q tile + K/V tile 0 ----
    {
        const __nv_bfloat16* gq =
            g_qb + ((size_t)(b * SEQ + qt * 64) * NH + h) * DHEAD;
        #pragma unroll
        for (int i = 0; i < 8; i++) {
            int idx = tid + i * 128;
            int r = idx >> 4, cc = idx & 15;
            cp_async16(Qs + r * ATT_STRIDE + cc * 16,
                       gq + (size_t)r * NH * DHEAD + cc * 8);
        }
        cp_commit();
    }
    auto load_kv = [&](int kt) {
        const size_t base = ((size_t)(b * SEQ + kt * 64) * NKV + kv) * DHEAD;
        #pragma unroll
        for (int i = 0; i < 8; i++) {
            int idx = tid + i * 128;
            int r = idx >> 4, cc = idx & 15;
            const size_t off = base + (size_t)r * NKV * DHEAD + cc * 8;
            const uint32_t d = r * ATT_STRIDE + cc * 16;
            cp_async16(Ks  + d, g_kb  + off);
            cp_async16(Vhs + d, g_vhb + off);
            cp_async16(Vls + d, g_vlb + off);
        }
        cp_commit();
    };
    load_kv(0);
    asm volatile("cp.async.wait_group 0;");
    __syncthreads();

    // ---- Q fragments (kept in registers for whole kernel) ----
    uint32_t qf[8][4];
    {
        const int a_row  = wid * 16 + ((lane >> 3) & 1) * 8 + (lane & 7);
        const int a_koff = ((lane >> 4) & 1) * 16;
        #pragma unroll
        for (int ks = 0; ks < 8; ks++)
            ldmx4(qf[ks], Qs + (uint32_t)a_row * ATT_STRIDE + ks * 32 + a_koff);
    }

    float o[16][4];
    #pragma unroll
    for (int dt = 0; dt < 16; dt++)
        #pragma unroll
        for (int j = 0; j < 4; j++) o[dt][j] = 0.f;
    float m0 = NEG_BIG, m1 = NEG_BIG, l0 = 0.f, l1 = 0.f;

    const int krow  = lane & 7;           // ldmx2 source row (lanes 0-15 matter)
    const int kko   = ((lane >> 3) & 1) * 16;
    const int vrow  = lane & 15;          // ldmx2t source row

    for (int kt = 0; kt <= qt; kt++) {
        // ---- scores: S = Q K^T ----
        float accs[8][4];
        #pragma unroll
        for (int nt = 0; nt < 8; nt++)
            #pragma unroll
            for (int j = 0; j < 4; j++) accs[nt][j] = 0.f;

        #pragma unroll
        for (int ks = 0; ks < 8; ks++) {
            #pragma unroll
            for (int nt = 0; nt < 8; nt++) {
                uint32_t kf[2];
                ldmx2(kf, Ks + (uint32_t)(nt * 8 + krow) * ATT_STRIDE + ks * 32 + kko);
                mma16816(accs[nt], qf[ks], kf);
            }
        }

        // ---- causal mask on diagonal tile ----
        if (kt == qt) {
            const int r0 = wid * 16 + (lane >> 2);
            const int r1 = r0 + 8;
            #pragma unroll
            for (int nt = 0; nt < 8; nt++) {
                const int c0 = nt * 8 + (lane & 3) * 2;
                if (c0 > r0)     accs[nt][0] = NEG_BIG;
                if (c0 + 1 > r0) accs[nt][1] = NEG_BIG;
                if (c0 > r1)     accs[nt][2] = NEG_BIG;
                if (c0 + 1 > r1) accs[nt][3] = NEG_BIG;
            }
        }

        // ---- online softmax ----
        float tm0 = NEG_BIG, tm1 = NEG_BIG;
        #pragma unroll
        for (int nt = 0; nt < 8; nt++) {
            tm0 = fmaxf(tm0, fmaxf(accs[nt][0], accs[nt][1]));
            tm1 = fmaxf(tm1, fmaxf(accs[nt][2], accs[nt][3]));
        }
        tm0 = fmaxf(tm0, __shfl_xor_sync(0xFFFFFFFF, tm0, 1));
        tm0 = fmaxf(tm0, __shfl_xor_sync(0xFFFFFFFF, tm0, 2));
        tm1 = fmaxf(tm1, __shfl_xor_sync(0xFFFFFFFF, tm1, 1));
        tm1 = fmaxf(tm1, __shfl_xor_sync(0xFFFFFFFF, tm1, 2));
        const float mn0 = fmaxf(m0, tm0);
        const float mn1 = fmaxf(m1, tm1);
        const float sc0 = __expf(m0 - mn0);
        const float sc1 = __expf(m1 - mn1);

        float ls0 = 0.f, ls1 = 0.f;
        #pragma unroll
        for (int nt = 0; nt < 8; nt++) {
            accs[nt][0] = __expf(accs[nt][0] - mn0);
            accs[nt][1] = __expf(accs[nt][1] - mn0);
            accs[nt][2] = __expf(accs[nt][2] - mn1);
            accs[nt][3] = __expf(accs[nt][3] - mn1);
            ls0 += accs[nt][0] + accs[nt][1];
            ls1 += accs[nt][2] + accs[nt][3];
        }
        ls0 += __shfl_xor_sync(0xFFFFFFFF, ls0, 1);
        ls0 += __shfl_xor_sync(0xFFFFFFFF, ls0, 2);
        ls1 += __shfl_xor_sync(0xFFFFFFFF, ls1, 1);
        ls1 += __shfl_xor_sync(0xFFFFFFFF, ls1, 2);
        l0 = l0 * sc0 + ls0;  m0 = mn0;
        l1 = l1 * sc1 + ls1;  m1 = mn1;

        #pragma unroll
        for (int dt = 0; dt < 16; dt++) {
            o[dt][0] *= sc0; o[dt][1] *= sc0;
            o[dt][2] *= sc1; o[dt][3] *= sc1;
        }

        // ---- O += P V  (P hi/lo x V hi/lo, 3 terms) ----
        #pragma unroll
        for (int ks = 0; ks < 4; ks++) {
            const int t0 = 2 * ks, t1 = 2 * ks + 1;
            uint32_t pha[4], pla[4];
            #pragma unroll
            for (int q = 0; q < 4; q++) {
                const float x0 = accs[(q & 2) ? t1 : t0][(q & 1) ? 2 : 0];
                const float x1 = accs[(q & 2) ? t1 : t0][(q & 1) ? 3 : 1];
                __nv_bfloat16 h0 = __float2bfloat16(x0);
                __nv_bfloat16 h1 = __float2bfloat16(x1);
                pha[q] = pack_bf2(h0, h1);
                pla[q] = pack_bf2(__float2bfloat16(x0 - __bfloat162float(h0)),
                                  __float2bfloat16(x1 - __bfloat162float(h1)));
            }
            #pragma unroll
            for (int dt = 0; dt < 16; dt++) {
                uint32_t vh[2], vl[2];
                const uint32_t va = (uint32_t)(ks * 16 + vrow) * ATT_STRIDE + dt * 16;
                ldmx2t(vh, Vhs + va);
                ldmx2t(vl, Vls + va);
                mma16816(o[dt], pha, vh);
                mma16816(o[dt], pha, vl);
                mma16816(o[dt], pla, vh);
            }
        }

        // ---- prefetch next K/V tile ----
        if (kt < qt) {
            __syncthreads();
            load_kv(kt + 1);
            asm volatile("cp.async.wait_group 0;");
            __syncthreads();
        }
    }

    // ---- epilogue: normalize, split hi/lo, write ctx ----
    const float inv0 = 1.f / l0;
    const float inv1 = 1.f / l1;
    const int tok0 = b * SEQ + qt * 64 + wid * 16 + (lane >> 2);
    const int tok1 = tok0 + 8;
    #pragma unroll
    for (int dt = 0; dt < 16; dt++) {
        const int col = h * DHEAD + dt * 8 + (lane & 3) * 2;
        const float x0 = o[dt][0] * inv0, x1 = o[dt][1] * inv0;
        const float y0 = o[dt][2] * inv1, y1 = o[dt][3] * inv1;
        __nv_bfloat16 xh0 = __float2bfloat16(x0), xh1 = __float2bfloat16(x1);
        __nv_bfloat16 yh0 = __float2bfloat16(y0), yh1 = __float2bfloat16(y1);
        const size_t i0 = (size_t)tok0 * HDIM + col;
        const size_t i1 = (size_t)tok1 * HDIM + col;
        *(uint32_t*)(g_ctx_hi + i0) = pack_bf2(xh0, xh1);
        *(uint32_t*)(g_ctx_lo + i0) = pack_bf2(
            __float2bfloat16(x0 - __bfloat162float(xh0)),
            __float2bfloat16(x1 - __bfloat162float(xh1)));
        *(uint32_t*)(g_ctx_hi + i1) = pack_bf2(yh0, yh1);
        *(uint32_t*)(g_ctx_lo + i1) = pack_bf2(
            __float2bfloat16(y0 - __bfloat162float(yh0)),
            __float2bfloat16(y1 - __bfloat162float(yh1)));
    }
}

// ---------------------------------------------------------------------------
// Launch
// ---------------------------------------------------------------------------
extern "C" void kernel_launch(void* const* d_in, const int* in_sizes, int n_in,
                              void* d_out, int out_size) {
    const int*   positions    = (const int*)  d_in[0];
    const float* hidden       = (const float*)d_in[1];
    const float* kv_cache_in  = (const float*)d_in[2];
    const int*   slot_mapping = (const int*)  d_in[4];
    const float* w_qkv = (const float*)d_in[n_in - 3];
    const float* b_qkv = (const float*)d_in[n_in - 2];
    const float* w_o   = (const float*)d_in[n_in - 1];

    float* out       = (float*)d_out;
    float* cache_out = out + (size_t)T_TOK * HDIM;

    float* qkv_ptr; cudaGetSymbolAddress((void**)&qkv_ptr, g_qkv);
    __nv_bfloat16 *hid_hi, *hid_lo, *wqkv_hi, *wqkv_lo, *wo_hi, *wo_lo, *ctx_hi, *ctx_lo;
    cudaGetSymbolAddress((void**)&hid_hi,  g_hid_hi);
    cudaGetSymbolAddress((void**)&hid_lo,  g_hid_lo);
    cudaGetSymbolAddress((void**)&wqkv_hi, g_wqkv_hi);
    cudaGetSymbolAddress((void**)&wqkv_lo, g_wqkv_lo);
    cudaGetSymbolAddress((void**)&wo_hi,   g_wo_hi);
    cudaGetSymbolAddress((void**)&wo_lo,   g_wo_lo);
    cudaGetSymbolAddress((void**)&ctx_hi,  g_ctx_hi);
    cudaGetSymbolAddress((void**)&ctx_lo,  g_ctx_lo);

    cudaFuncSetAttribute(gemm_bf16x3,
                         cudaFuncAttributeMaxDynamicSharedMemorySize, GSMEM_BYTES);
    cudaFuncSetAttribute(attn_mma,
                         cudaFuncAttributeMaxDynamicSharedMemorySize, ATT_SMEM);

    // 1) Seed output cache with the input cache
    cudaMemcpyAsync(cache_out, kv_cache_in,
                    (size_t)2 * NSLOTS * NKV * DHEAD * sizeof(float),
                    cudaMemcpyDeviceToDevice, 0);

    // 2) Split hidden + w_qkv + w_o into bf16 hi/lo
    {
        int n4 = (T_TOK * HDIM) / 4;
        split_f32_bf16<<<(n4 + 255) / 256, 256>>>((const float4*)hidden,
                                                  (uint2*)hid_hi, (uint2*)hid_lo, n4);
        n4 = (QKV_OUT * HDIM) / 4;
        split_f32_bf16<<<(n4 + 255) / 256, 256>>>((const float4*)w_qkv,
                                                  (uint2*)wqkv_hi, (uint2*)wqkv_lo, n4);
        n4 = (HDIM * HDIM) / 4;
        split_f32_bf16<<<(n4 + 255) / 256, 256>>>((const float4*)w_o,
                                                  (uint2*)wo_hi, (uint2*)wo_lo, n4);
    }

    // 3) QKV projection (tensor cores)
    {
        dim3 grid(QKV_OUT / 128, T_TOK / 128);
        gemm_bf16x3<<<grid, 256, GSMEM_BYTES>>>(hid_hi, hid_lo, wqkv_hi, wqkv_lo,
                                                b_qkv, qkv_ptr,
                                                T_TOK, QKV_OUT, HDIM);
    }

    // 4) RoPE + cache scatter + bf16 mirrors
    rope_scatter_kernel<<<T_TOK, 128>>>(positions, slot_mapping, cache_out);

    // 5) Tensor-core flash attention -> ctx_hi/ctx_lo
    {
        dim3 grid(SEQ / 64, BATCH * NH);
        attn_mma<<<grid, 128, ATT_SMEM>>>(nullptr);
    }

    // 6) Output projection (tensor cores)
    {
        dim3 grid(HDIM / 128, T_TOK / 128);
        gemm_bf16x3<<<grid, 256, GSMEM_BYTES>>>(ctx_hi, ctx_lo, wo_hi, wo_lo,
                                                nullptr, out,
                                                T_TOK, HDIM, NH * DHEAD);
    }
}